// round 17
// baseline (speedup 1.0000x reference)
#include <cuda_runtime.h>
#include <cuda_fp16.h>

#define H_ 512
#define W_ 512
#define C_ 32
#define B_ 2
#define N_ 120000
#define HW_ (H_*W_)
#define NP_ (B_*N_)

typedef unsigned long long u64;

// ---- device scratch (no allocations allowed) ----
__device__ __align__(128) float  g_Q[NP_*C_];
__device__ __align__(128) __half g_KV[NP_*64];       // per-point 128B row: K[32] fp16, V[32] fp16
__device__ __align__(128) float  g_Osp[B_*HW_*C_];   // spatial O (only valid cells written)
__device__ int   g_grid[B_*HW_];
__device__ u64   g_A2p[32*48];    // channel-pair packed: [e][m*16+j] = (A[2j][e],A[2j+1][e])
__device__ u64   g_bf2[48];       // packed bias pairs
__device__ u64   g_posP2[9*16];   // pair-packed posP
__device__ __align__(128) __half g_kvinvh[64];       // fp16: kinv[32] | vinv[32]

// ---- packed f32x2 helpers ----
__device__ __forceinline__ u64 pk2(float lo, float hi){
    u64 r; asm("mov.b64 %0, {%1, %2};" : "=l"(r) : "f"(lo), "f"(hi)); return r;
}
__device__ __forceinline__ float2 unpk2(u64 v){
    float2 f; asm("mov.b64 {%0, %1}, %2;" : "=f"(f.x), "=f"(f.y) : "l"(v)); return f;
}
__device__ __forceinline__ u64 ffma2(u64 a, u64 b, u64 c){
    u64 d; asm("fma.rn.f32x2 %0, %1, %2, %3;" : "=l"(d) : "l"(a), "l"(b), "l"(c)); return d;
}
__device__ __forceinline__ u64 add2(u64 a, u64 b){
    u64 d; asm("add.rn.f32x2 %0, %1, %2;" : "=l"(d) : "l"(a), "l"(b)); return d;
}
__device__ __forceinline__ u64 mul2(u64 a, u64 b){
    u64 d; asm("mul.rn.f32x2 %0, %1, %2;" : "=l"(d) : "l"(a), "l"(b)); return d;
}
__device__ __forceinline__ float hsum2(u64 a){ float2 f = unpk2(a); return f.x + f.y; }
__device__ __forceinline__ u64 h2f2(unsigned v){
    __half2 h = *reinterpret_cast<__half2*>(&v);
    float2 f = __half22float2(h);
    return pk2(f.x, f.y);
}

// ---------------------------------------------------------------
// K0: block 0 = weight fold + pack entirely from smem; blocks 1.. = grid clear
// ---------------------------------------------------------------
__global__ void __launch_bounds__(256) k_setup(
                        const float* __restrict__ wq, const float* __restrict__ bq,
                        const float* __restrict__ wk, const float* __restrict__ bk,
                        const float* __restrict__ wv, const float* __restrict__ bv,
                        const float* __restrict__ in_w, const float* __restrict__ in_b,
                        const float* __restrict__ pos_w, const float* __restrict__ pos_b){
    int t = threadIdx.x;
    if (blockIdx.x > 0){
        g_grid[(blockIdx.x - 1)*256 + t] = -1;   // 2048 blocks * 256 = B_*HW_
        return;
    }
    __shared__ float sW[3*1024];    // wq | wk | wv
    __shared__ float sIW[3*1024];   // in_w
    __shared__ float sA[3*1024];    // folded A
    __shared__ float sB[96];        // bq | bk | bv
    __shared__ float sINB[96];
    __shared__ float sPW[64], sPB[32];
    __shared__ float sBF[96];
    __shared__ float sPP[288];
    for (int i = t; i < 1024; i += 256){
        sW[i] = wq[i]; sW[1024 + i] = wk[i]; sW[2048 + i] = wv[i];
        sIW[i] = in_w[i]; sIW[1024 + i] = in_w[1024 + i]; sIW[2048 + i] = in_w[2048 + i];
    }
    if (t < 32){ sB[t] = bq[t]; sB[32+t] = bk[t]; sB[64+t] = bv[t]; }
    if (t >= 32 && t < 128) sINB[t-32] = in_b[t-32];
    if (t >= 128 && t < 192) sPW[t-128] = pos_w[t-128];
    if (t >= 192 && t < 224) sPB[t-192] = pos_b[t-192];
    __syncthreads();

    for (int idx = t; idx < 3072; idx += 256){
        int m = idx >> 10, rem = idx & 1023, c = rem >> 5, e = rem & 31;
        const float* iw = sIW + (m*32 + c)*32;
        const float* Wm = sW + m*1024;
        float a = 0.f;
#pragma unroll
        for (int d = 0; d < 32; d++) a += iw[d] * Wm[d*32 + e];
        sA[m*1024 + c*32 + e] = (m==0) ? a*0.25f : a;
    }
    if (t < 96){
        int m = t >> 5;
        const float* iw = sIW + t*32;
        float bb = 0.f;
#pragma unroll
        for (int d = 0; d < 32; d++) bb += iw[d] * sB[m*32 + d];
        bb += sINB[t];
        sBF[t] = (m==0) ? bb*0.25f : bb;
    }
    {
        const float drf[9] = {0,-1,1,0,-1,1,0,-1,1};
        const float dcf[9] = {0,0,0,1,1,1,-1,-1,-1};
        for (int idx = t; idx < 288; idx += 256){
            int s = idx >> 5, c = idx & 31;
            const float* iw = sIW + (64 + c)*32;
            float a = 0.f;
#pragma unroll
            for (int d = 0; d < 32; d++){
                float pos = drf[s]*sPW[d*2+0] + dcf[s]*sPW[d*2+1] + sPB[d];
                a += iw[d] * pos;
            }
            sPP[s*32 + c] = a;
        }
    }
    __syncthreads();
    for (int idx = t; idx < 1536; idx += 256){
        int e = idx & 31, jj = idx >> 5;
        int m = jj >> 4, j = jj & 15;
        g_A2p[e*48 + jj] = pk2(sA[(m*32 + 2*j)*32 + e], sA[(m*32 + 2*j + 1)*32 + e]);
    }
    if (t < 48){
        int m = t >> 4, j = t & 15;
        g_bf2[t] = pk2(sBF[m*32 + 2*j], sBF[m*32 + 2*j + 1]);
    }
    if (t >= 64 && t < 208){
        int u = t - 64;
        int s = u >> 4, k = u & 15;
        g_posP2[u] = pk2(sPP[s*32 + 2*k], sPP[s*32 + 2*k + 1]);
    }
    if (t >= 224){   // kinv|vinv rows as fp16 (in_b[32..95])
        int u = t - 224;      // 0..31 -> 2 halves each
        g_kvinvh[2*u]   = __float2half(sINB[32 + 2*u]);
        g_kvinvh[2*u+1] = __float2half(sINB[32 + 2*u + 1]);
    }
}

// ---------------------------------------------------------------
// K1: LN + fused QKV GEMM (channel-pair packed, no transpose) + grid fill.
// ---------------------------------------------------------------
__global__ void __launch_bounds__(256) k_qkv(const float* __restrict__ feats,
                                             const float* __restrict__ ln_w,
                                             const float* __restrict__ ln_b,
                                             const int* __restrict__ coors){
    __shared__ __align__(16) u64   shA2p[32*48];   // 12KB
    __shared__ __align__(16) float Xs[32*128];     // 16KB
    __shared__ __align__(16) u64   shBp[48];
    int t = threadIdx.x;
    int p0 = blockIdx.x*128;
    if (t >= 128){
        int u = t - 128;
#pragma unroll
        for (int it = 0; it < 12; it++) shA2p[u + 128*it] = g_A2p[u + 128*it];
        if (u < 48) shBp[u] = g_bf2[u];
    } else {
        int p = p0 + t;   // 1875*128 == 240000 exact
        {
            int r = __ldg(&coors[2*p]), c = __ldg(&coors[2*p+1]);
            int b = p / N_;
            g_grid[b*HW_ + r*W_ + c] = p - b*N_;
        }
        const float4* xin = (const float4*)(feats + (size_t)p*C_);
        float x[32];
#pragma unroll
        for (int k = 0; k < 8; k++){
            float4 v = xin[k];
            x[4*k] = v.x; x[4*k+1] = v.y; x[4*k+2] = v.z; x[4*k+3] = v.w;
        }
        float mu = 0.f;
#pragma unroll
        for (int e = 0; e < 32; e++) mu += x[e];
        mu *= (1.f/32.f);
        float var = 0.f;
#pragma unroll
        for (int e = 0; e < 32; e++){ float d = x[e]-mu; var += d*d; }
        var *= (1.f/32.f);
        float inv = rsqrtf(var + 1e-5f);
#pragma unroll
        for (int k = 0; k < 32; k++)
            Xs[k*128 + t] = (x[k]-mu)*inv*__ldg(&ln_w[k]) + __ldg(&ln_b[k]);
    }
    __syncthreads();

    int i = t >> 4, j = t & 15;
    u64 acc0[8], acc1[8], acc2[8];
    {
        u64 b0 = shBp[j], b1 = shBp[16 + j], b2 = shBp[32 + j];
#pragma unroll
        for (int p8 = 0; p8 < 8; p8++){ acc0[p8] = b0; acc1[p8] = b1; acc2[p8] = b2; }
    }
#pragma unroll 2
    for (int e = 0; e < 32; e++){
        const float4* xr = (const float4*)(Xs + e*128) + i*2;
        float4 xa = xr[0], xb = xr[1];
        u64 xd[8];
        xd[0] = pk2(xa.x, xa.x); xd[1] = pk2(xa.y, xa.y);
        xd[2] = pk2(xa.z, xa.z); xd[3] = pk2(xa.w, xa.w);
        xd[4] = pk2(xb.x, xb.x); xd[5] = pk2(xb.y, xb.y);
        xd[6] = pk2(xb.z, xb.z); xd[7] = pk2(xb.w, xb.w);
        u64 a0 = shA2p[e*48 + j];
        u64 a1 = shA2p[e*48 + 16 + j];
        u64 a2 = shA2p[e*48 + 32 + j];
#pragma unroll
        for (int p8 = 0; p8 < 8; p8++){
            acc0[p8] = ffma2(a0, xd[p8], acc0[p8]);
            acc1[p8] = ffma2(a1, xd[p8], acc1[p8]);
            acc2[p8] = ffma2(a2, xd[p8], acc2[p8]);
        }
    }
    int prow = p0 + 8*i;
#pragma unroll
    for (int p8 = 0; p8 < 8; p8++)
        *(u64*)(g_Q + (size_t)(prow+p8)*C_ + 2*j) = acc0[p8];
#pragma unroll
    for (int p8 = 0; p8 < 8; p8++){
        float2 fk = unpk2(acc1[p8]);
        float2 fv = unpk2(acc2[p8]);
        __half* row = g_KV + (size_t)(prow+p8)*64;
        *(__half2*)(row + 2*j)      = __floats2half2_rn(fk.x, fk.y);
        *(__half2*)(row + 32 + 2*j) = __floats2half2_rn(fv.x, fv.y);
    }
}

// ---------------------------------------------------------------
// K2: attention with WARP-COOPERATIVE KV gather.
//     8 lanes per point: lanes 0-3 hold K chunks (+q), lanes 4-7 hold V
//     chunks. Coalesced 128B row loads; shfl logit reduce + weight bcast.
//     Then the (unchanged) output-projection GEMM + spatial-O store.
// ---------------------------------------------------------------
__global__ void __launch_bounds__(256) k_attn(const int* __restrict__ coors,
                                              const float* __restrict__ out_w,
                                              const float* __restrict__ out_b){
    __shared__ __align__(16) u64   shWt2[32*32];        // 8KB
    __shared__ __align__(16) float shOs[32*260];        // 33.3KB
    __shared__ __align__(16) u64   shPos2[9*16];
    __shared__ float shOB[32];
    __shared__ int   shHW[256];
    int t = threadIdx.x;
#pragma unroll
    for (int it = 0; it < 4; it++){
        int idx2 = t + 256*it;
        int k = idx2 >> 5, c = idx2 & 31;
        float w = out_w[c*32 + k];
        shWt2[idx2] = pk2(w, w);
    }
    if (t < 144) shPos2[t] = g_posP2[t];
    if (t >= 224){ int u = t-224; shOB[u] = out_b[u]; }
    __syncthreads();

    int pbase = blockIdx.x*256;
    int w  = t >> 5, lane = t & 31;
    int g  = lane >> 3, l = lane & 7;
    int base = lane & 24;              // g*8
    int li = l & 3;

    const uint4* invp = ((const uint4*)g_kvinvh) + l;

    // neighbor offsets for s = l (0..7) computed arithmetically (no dyn array)
    int d3 = (l*11) >> 5;              // l/3 for l<9
    int r3 = l - 3*d3;
    int drl = (r3==1) ? -1 : ((r3==2) ? 1 : 0);
    int dcl = (d3==1) ?  1 : ((d3==2) ? -1 : 0);

    for (int pp = 0; pp < 8; pp++){
        int plocal = w*32 + pp*4 + g;          // 0..255
        int p  = pbase + plocal;
        int pc = (p < NP_) ? p : (NP_ - 1);
        int b  = pc / N_;
        int r0 = __ldg(&coors[2*pc]), c0 = __ldg(&coors[2*pc+1]);
        if (l == 0) shHW[plocal] = b*HW_ + r0*W_ + c0;
        const int* grid = g_grid + b*HW_;

        int ia, ib = -1;
        {
            int rr = r0 + drl, cc = c0 + dcl;
            bool ok = (rr >= 0) & (rr < H_) & (cc >= 0) & (cc < W_);
            ia = ok ? __ldg(&grid[rr*W_ + cc]) : -1;
            if (l == 0){
                int rr2 = r0 + 1, cc2 = c0 - 1;   // s=8: (1,-1)
                bool ok2 = (rr2 < H_) & (cc2 >= 0);
                ib = ok2 ? __ldg(&grid[rr2*W_ + cc2]) : -1;
            }
        }
        // q pairs: lane holds q[8*li .. 8*li+8) (V lanes mirror K lanes; dedup'd)
        u64 qpr[4];
        {
            const float4* q4 = (const float4*)(g_Q + (size_t)pc*32);
            float4 f1 = q4[2*li], f2 = q4[2*li+1];
            qpr[0] = pk2(f1.x, f1.y); qpr[1] = pk2(f1.z, f1.w);
            qpr[2] = pk2(f2.x, f2.y); qpr[3] = pk2(f2.z, f2.w);
        }
        float sum = 0.f;
        u64 ov[4] = {0ull, 0ull, 0ull, 0ull};
        const __half* kvb = g_KV + (size_t)b*N_*64;

#pragma unroll
        for (int s = 0; s < 9; s++){
            int idx_s = (s < 8) ? __shfl_sync(0xffffffffu, ia, base + s)
                                : __shfl_sync(0xffffffffu, ib, base);
            bool val = idx_s >= 0;
            const uint4* ptr = val ? ((const uint4*)(kvb + (size_t)idx_s*64)) + l : invp;
            uint4 d = *ptr;
            u64 c0_ = h2f2(d.x), c1_ = h2f2(d.y), c2_ = h2f2(d.z), c3_ = h2f2(d.w);
            // logit partial (meaningful on lanes 0-3)
            u64 a = ffma2(qpr[0], c0_, 0ull);
            u64 b2 = ffma2(qpr[1], c1_, 0ull);
            a  = ffma2(qpr[2], c2_, a);
            b2 = ffma2(qpr[3], c3_, b2);
            float pl = hsum2(add2(a, b2));
            pl += __shfl_xor_sync(0xffffffffu, pl, 1);
            float wgt = __expf(pl);
            float wv = __shfl_sync(0xffffffffu, wgt, base + (l & 2));
            sum += wv;
            float fl = val ? 1.f : 0.f;
            u64 W = pk2(wv, wv), F = pk2(fl, fl);
            const u64* ppos = shPos2 + s*16 + (li << 2);
            ov[0] = ffma2(W, ffma2(F, ppos[0], c0_), ov[0]);
            ov[1] = ffma2(W, ffma2(F, ppos[1], c1_), ov[1]);
            ov[2] = ffma2(W, ffma2(F, ppos[2], c2_), ov[2]);
            ov[3] = ffma2(W, ffma2(F, ppos[3], c3_), ov[3]);
        }
        if (l >= 4){
            float rs = 1.f/sum;
            u64 R = pk2(rs, rs);
            int chb = li*8;
#pragma unroll
            for (int k2 = 0; k2 < 4; k2++){
                float2 fo = unpk2(mul2(ov[k2], R));
                shOs[(chb + 2*k2    )*260 + plocal] = fo.x;
                shOs[(chb + 2*k2 + 1)*260 + plocal] = fo.y;
            }
        }
    }
    __syncthreads();

    // output projection GEMM: thread (i,j): points 8i.. (4 pairs), channels {j+8cc}
    int i = t >> 3, j = t & 7;
    u64 acc[4][4];
#pragma unroll
    for (int cc = 0; cc < 4; cc++){
        float bb = shOB[j + 8*cc];
        u64 b2 = pk2(bb, bb);
#pragma unroll
        for (int mm = 0; mm < 4; mm++) acc[cc][mm] = b2;
    }
#pragma unroll 4
    for (int e = 0; e < 32; e++){
        const u64* xr = (const u64*)(shOs + e*260) + i*4;
        ulonglong2 xa = *(const ulonglong2*)(xr);
        ulonglong2 xb = *(const ulonglong2*)(xr + 2);
        u64 xv[4] = {xa.x, xa.y, xb.x, xb.y};
        const u64* wr = shWt2 + e*32 + j;
        u64 av[4];
#pragma unroll
        for (int cc = 0; cc < 4; cc++) av[cc] = wr[8*cc];
#pragma unroll
        for (int cc = 0; cc < 4; cc++)
#pragma unroll
            for (int mm = 0; mm < 4; mm++)
                acc[cc][mm] = ffma2(av[cc], xv[mm], acc[cc][mm]);
    }
#pragma unroll
    for (int cc = 0; cc < 4; cc++)
#pragma unroll
        for (int mm = 0; mm < 4; mm++){
            int lidx = 8*i + 2*mm;
            int pt = pbase + lidx;
            if (pt < NP_){   // pt even, NP_ even -> pt+1 < NP_ too
                float2 f = unpk2(acc[cc][mm]);
                g_Osp[(size_t)shHW[lidx  ]*C_ + j + 8*cc] = f.x;
                g_Osp[(size_t)shHW[lidx+1]*C_ + j + 8*cc] = f.y;
            }
        }
}

// ---------------------------------------------------------------
// K3: expand to [B,C,H,W]
// ---------------------------------------------------------------
__global__ void __launch_bounds__(256) k_expand(float* __restrict__ out){
    __shared__ float sm[256*33];
    int b   = blockIdx.y;
    int hw0 = blockIdx.x * 256;
    int t   = threadIdx.x;
    int hw  = hw0 + t;
    int idx = g_grid[b*HW_ + hw];
    if (idx >= 0){
        const float4* orow = (const float4*)(g_Osp + ((size_t)b*HW_ + hw)*C_);
#pragma unroll
        for (int k = 0; k < 8; k++){
            float4 v = orow[k];
            sm[t*33 + 4*k + 0] = v.x; sm[t*33 + 4*k + 1] = v.y;
            sm[t*33 + 4*k + 2] = v.z; sm[t*33 + 4*k + 3] = v.w;
        }
    } else {
#pragma unroll
        for (int c = 0; c < 32; c++) sm[t*33 + c] = 0.f;
    }
    __syncthreads();
#pragma unroll
    for (int c = 0; c < 32; c++)
        out[((size_t)(b*C_ + c))*HW_ + hw] = sm[t*33 + c];
}

// ---------------------------------------------------------------
extern "C" void kernel_launch(void* const* d_in, const int* in_sizes, int n_in,
                              void* d_out, int out_size){
    const float* feats = (const float*)d_in[0];
    const int*   coors = (const int*)  d_in[1];
    const float* ln_w  = (const float*)d_in[2];
    const float* ln_b  = (const float*)d_in[3];
    const float* wq    = (const float*)d_in[4];
    const float* bq    = (const float*)d_in[5];
    const float* wk    = (const float*)d_in[6];
    const float* bk    = (const float*)d_in[7];
    const float* wv    = (const float*)d_in[8];
    const float* bv    = (const float*)d_in[9];
    const float* pos_w = (const float*)d_in[10];
    const float* pos_b = (const float*)d_in[11];
    const float* in_w  = (const float*)d_in[12];
    const float* in_b  = (const float*)d_in[13];
    const float* out_w = (const float*)d_in[14];
    const float* out_b = (const float*)d_in[15];

    k_setup<<<1 + B_*HW_/256, 256>>>(wq, bq, wk, bk, wv, bv, in_w, in_b, pos_w, pos_b);
    k_qkv<<<NP_/128, 256>>>(feats, ln_w, ln_b, coors);
    k_attn<<<(NP_ + 255)/256, 256>>>(coors, out_w, out_b);
    k_expand<<<dim3(HW_/256, B_), 256>>>((float*)d_out);
}